// round 9
// baseline (speedup 1.0000x reference)
#include <cuda_runtime.h>
#include <cstdint>

typedef unsigned long long ull;
#define FULLM 0xffffffffu

#define NQ 8
#define DIM 256
#define NW 16
#define NB 16
#define NROTS 64
#define EMB 512
#define NVOCAB 50257
#define NOUT_OP (NB*NVOCAB)

// ---------------- scratch ----------------
__device__ float g_fp[NB];
__device__ __align__(16) float g_h[NB*EMB];   // h[b][k]

// ---------------- f32x2 helpers ----------------
__device__ __forceinline__ ull pack2(float a, float b){
    ull r; asm("mov.b64 %0, {%1,%2};" : "=l"(r) : "f"(a), "f"(b)); return r;
}
__device__ __forceinline__ void unpack2(ull v, float &a, float &b){
    asm("mov.b64 {%0,%1}, %2;" : "=f"(a), "=f"(b) : "l"(v));
}
__device__ __forceinline__ void fma2(ull &d, ull a, ull b){
    asm("fma.rn.f32x2 %0, %1, %2, %0;" : "+l"(d) : "l"(a), "l"(b));
}
__device__ __forceinline__ ull add2(ull a, ull b){
    ull r; asm("add.rn.f32x2 %0, %1, %2;" : "=l"(r) : "l"(a), "l"(b)); return r;
}

// =====================================================================
// Warp-resident quantum gates. amp index a = lane*8 + r
// =====================================================================
template<int P>
__device__ __forceinline__ void ry_gate(float2* s, float c, float sn, int lane){
    if constexpr (P < 3){
        #pragma unroll
        for (int r = 0; r < 8; r++)
            if (!(r & (1<<P))){
                const int r1 = r | (1<<P);
                float2 a0 = s[r], a1 = s[r1];
                s[r]  = make_float2(c*a0.x - sn*a1.x, c*a0.y - sn*a1.y);
                s[r1] = make_float2(sn*a0.x + c*a1.x, sn*a0.y + c*a1.y);
            }
    } else {
        const int M = 1 << (P-3);
        float sg = (lane & M) ? sn : -sn;
        #pragma unroll
        for (int r = 0; r < 8; r++){
            float px = __shfl_xor_sync(FULLM, s[r].x, M);
            float py = __shfl_xor_sync(FULLM, s[r].y, M);
            s[r] = make_float2(c*s[r].x + sg*px, c*s[r].y + sg*py);
        }
    }
}

template<int PC, int PT>
__device__ __forceinline__ void crx_gate(float2* s, float c, float sn, int lane){
    if constexpr (PT < 3 && PC < 3){
        #pragma unroll
        for (int r = 0; r < 8; r++)
            if ((r & (1<<PC)) && !(r & (1<<PT))){
                const int r1 = r | (1<<PT);
                float2 a0 = s[r], a1 = s[r1];
                s[r]  = make_float2(c*a0.x + sn*a1.y, c*a0.y - sn*a1.x);
                s[r1] = make_float2(c*a1.x + sn*a0.y, c*a1.y - sn*a0.x);
            }
    } else if constexpr (PT < 3 && PC >= 3){
        if (lane & (1 << (PC-3))){
            #pragma unroll
            for (int r = 0; r < 8; r++)
                if (!(r & (1<<PT))){
                    const int r1 = r | (1<<PT);
                    float2 a0 = s[r], a1 = s[r1];
                    s[r]  = make_float2(c*a0.x + sn*a1.y, c*a0.y - sn*a1.x);
                    s[r1] = make_float2(c*a1.x + sn*a0.y, c*a1.y - sn*a0.x);
                }
        }
    } else if constexpr (PT >= 3 && PC < 3){
        const int M = 1 << (PT-3);
        #pragma unroll
        for (int r = 0; r < 8; r++){
            float px = __shfl_xor_sync(FULLM, s[r].x, M);
            float py = __shfl_xor_sync(FULLM, s[r].y, M);
            if (r & (1<<PC))
                s[r] = make_float2(c*s[r].x + sn*py, c*s[r].y - sn*px);
        }
    } else {
        const int M = 1 << (PT-3);
        bool ctl = (lane & (1 << (PC-3))) != 0;
        #pragma unroll
        for (int r = 0; r < 8; r++){
            float px = __shfl_xor_sync(FULLM, s[r].x, M);
            float py = __shfl_xor_sync(FULLM, s[r].y, M);
            if (ctl)
                s[r] = make_float2(c*s[r].x + sn*py, c*s[r].y - sn*px);
        }
    }
}

__device__ __forceinline__ void layer(float2* s, const float2* ang, int lane){
    float2 a;
    #define RYG(P, I)     { a = ang[I]; ry_gate<P>(s, a.x, a.y, lane); }
    #define CRXG(PC,PT,I) { a = ang[I]; crx_gate<PC,PT>(s, a.x, a.y, lane); }
    RYG(7,0) RYG(6,1) RYG(5,2) RYG(4,3) RYG(3,4) RYG(2,5) RYG(1,6) RYG(0,7)
    CRXG(0,7,8) CRXG(1,0,9) CRXG(2,1,10) CRXG(3,2,11)
    CRXG(4,3,12) CRXG(5,4,13) CRXG(6,5,14) CRXG(7,6,15)
    RYG(7,16) RYG(6,17) RYG(5,18) RYG(4,19) RYG(3,20) RYG(2,21) RYG(1,22) RYG(0,23)
    CRXG(0,1,24) CRXG(7,0,25) CRXG(6,7,26) CRXG(5,6,27)
    CRXG(4,5,28) CRXG(3,4,29) CRXG(2,3,30) CRXG(1,2,31)
    #undef RYG
    #undef CRXG
}

// =====================================================================
// Kernel 1: EVERYTHING except FF2. 16 blocks x 512 thr.
// Prologue computes wparams angles in-block (fused small GEMM).
// =====================================================================
union MidU {
    float2 embp[8][EMB];      // emb pairs: (emb[2wp][k], emb[2wp+1][k]) — 32 KB
    float2 st[NW][DIM];       // circuit states — 32 KB
};

__global__ void __launch_bounds__(512) mid_kernel(const int* __restrict__ x,
                           const float* __restrict__ embW,
                           const float* __restrict__ e2rW,
                           const float* __restrict__ e2rb,
                           const float* __restrict__ mix,
                           const float* __restrict__ poly,
                           const float* __restrict__ qff,
                           const float* __restrict__ ff1W,
                           const float* __restrict__ ff1b){
    __shared__ MidU u;                     // 32 KB
    __shared__ float2 sh_ang[NW][NROTS];   // 8 KB
    __shared__ float2 sh_comb[DIM];        // 2 KB
    __shared__ float2 sh_cf[NW];
    __shared__ float2 sh_qang[32];
    __shared__ float  redv[16];
    __shared__ float  red3[12];
    __shared__ float  exps[24];
    __shared__ float  sh_inv;

    int b = blockIdx.x;
    int t = threadIdx.x;
    int w = t >> 5, lane = t & 31;

    // ---- stage embedding pairs into smem ----
    {
        float* embf = (float*)u.embp;
        for (int idx = t; idx < NW*EMB; idx += 512){
            int w_ = idx >> 9, k = idx & 511;
            float val = embW[(size_t)x[b*NW + w_]*EMB + k];
            embf[((w_ >> 1)*EMB + k)*2 + (w_ & 1)] = val;
        }
    }
    if (t < 32){
        float re = 0.f, im = 0.f, a = 0.f;
        if (t < NW){ re = mix[2*t]; im = mix[2*t+1]; a = sqrtf(re*re + im*im); }
        float s = a;
        #pragma unroll
        for (int o = 16; o; o >>= 1) s += __shfl_xor_sync(FULLM, s, o);
        float inv = 1.f / fmaxf(s, 1e-12f);
        if (t < NW) sh_cf[t] = make_float2(re*inv, im*inv);
    }
    if (t >= 32 && t < 64){
        int i = t - 32;
        float sv, cv; sincosf(qff[i]*0.5f, &sv, &cv);
        sh_qang[i] = make_float2(cv, sv);
    }
    __syncthreads();

    // ---- fused wparams: warp wid computes rots r = w*4+rr for all 16 circuits ----
    {
        ull acc2[4][8];
        #pragma unroll
        for (int rr = 0; rr < 4; rr++)
            #pragma unroll
            for (int wp = 0; wp < 8; wp++) acc2[rr][wp] = 0ULL;

        #pragma unroll 4
        for (int it = 0; it < 16; it++){
            int k = it*32 + lane;
            float wr_[4];
            #pragma unroll
            for (int rr = 0; rr < 4; rr++)
                wr_[rr] = e2rW[(size_t)(w*4 + rr)*EMB + k];
            ull e2[8];
            #pragma unroll
            for (int wp = 0; wp < 8; wp++)
                e2[wp] = *(const ull*)&u.embp[wp][k];
            #pragma unroll
            for (int rr = 0; rr < 4; rr++){
                ull w2 = pack2(wr_[rr], wr_[rr]);
                #pragma unroll
                for (int wp = 0; wp < 8; wp++)
                    fma2(acc2[rr][wp], w2, e2[wp]);
            }
        }
        // all-reduce over lanes
        #pragma unroll
        for (int o = 16; o; o >>= 1)
            #pragma unroll
            for (int rr = 0; rr < 4; rr++)
                #pragma unroll
                for (int wp = 0; wp < 8; wp++)
                    acc2[rr][wp] = add2(acc2[rr][wp], __shfl_xor_sync(FULLM, acc2[rr][wp], o));
        // lane -> (rr = lane>>3, wp = lane&7), predicated select (no dyn indexing)
        int lrr = lane >> 3, lwp = lane & 7;
        ull v = 0ULL;
        #pragma unroll
        for (int rr = 0; rr < 4; rr++)
            #pragma unroll
            for (int wp = 0; wp < 8; wp++)
                if (rr == lrr && wp == lwp) v = acc2[rr][wp];
        int r = w*4 + lrr;
        float bias_r = e2rb[r];
        float lo, hi; unpack2(v, lo, hi);
        float s0, c0, s1, c1;
        sincosf((lo + bias_r)*0.5f, &s0, &c0);
        sincosf((hi + bias_r)*0.5f, &s1, &c1);
        sh_ang[2*lwp][r]     = make_float2(c0, s0);
        sh_ang[2*lwp + 1][r] = make_float2(c1, s1);
    }
    __syncthreads();

    // ---- 3 polynomial degrees of 16 circuits (warp w = circuit w) ----
    float2 pacc = make_float2((t == 0) ? poly[0] : 0.f, 0.f);

    #pragma unroll 1
    for (int d = 1; d <= 3; d++){
        float2 s[8];
        if (d == 1){
            #pragma unroll
            for (int r = 0; r < 8; r++)
                s[r] = make_float2((lane == 0 && r == 0) ? 1.f : 0.f, 0.f);
        } else {
            #pragma unroll
            for (int r = 0; r < 8; r++) s[r] = sh_comb[lane*8 + r];
        }
        #pragma unroll 1
        for (int l = 0; l < 2; l++)
            layer(s, &sh_ang[w][32*l], lane);
        #pragma unroll
        for (int r = 0; r < 8; r++) u.st[w][lane*8 + r] = s[r];
        __syncthreads();
        if (t < DIM){
            float2 acc2 = make_float2(0.f, 0.f);
            #pragma unroll
            for (int ww = 0; ww < NW; ww++){
                float2 c = sh_cf[ww];
                float2 v = u.st[ww][t];
                acc2.x += c.x*v.x - c.y*v.y;
                acc2.y += c.x*v.y + c.y*v.x;
            }
            float pd = poly[d];
            pacc.x += pd*acc2.x; pacc.y += pd*acc2.y;
            sh_comb[t] = acc2;
        }
        __syncthreads();
    }

    // ---- normalize + final probs ----
    float psum = fabsf(poly[0]) + fabsf(poly[1]) + fabsf(poly[2]) + fabsf(poly[3]);
    float invp = 1.f / psum;
    float2 m = make_float2(pacc.x*invp, pacc.y*invp);
    if (t < DIM){
        float loc = m.x*m.x + m.y*m.y;
        #pragma unroll
        for (int o = 16; o; o >>= 1) loc += __shfl_xor_sync(FULLM, loc, o);
        if (lane == 0) redv[w] = loc;
    }
    __syncthreads();
    if (t == 0){
        float fp = sqrtf(redv[0]+redv[1]+redv[2]+redv[3]+redv[4]+redv[5]+redv[6]+redv[7]);
        g_fp[b] = fp;
        sh_inv = 1.f / fmaxf(fp, 1e-12f);
    }
    __syncthreads();
    if (t < DIM) sh_comb[t] = make_float2(m.x*sh_inv, m.y*sh_inv);
    __syncthreads();

    // ---- qff circuit on warp 0 ----
    if (w == 0){
        float2 s[8];
        #pragma unroll
        for (int r = 0; r < 8; r++) s[r] = sh_comb[lane*8 + r];
        layer(s, sh_qang, lane);
        #pragma unroll
        for (int r = 0; r < 8; r++) sh_comb[lane*8 + r] = s[r];
    }
    __syncthreads();

    // ---- measure X/Y/Z ----
    for (int wq = 0; wq < 8; wq++){
        int p = 7 - wq;
        if (t < 128){
            int i0 = ((t >> p) << (p+1)) | (t & ((1 << p) - 1));
            int i1 = i0 | (1 << p);
            float2 a0 = sh_comb[i0], a1 = sh_comb[i1];
            float cr = a0.x*a1.x + a0.y*a1.y;
            float ci = a0.x*a1.y - a0.y*a1.x;
            float zz = (a0.x*a0.x + a0.y*a0.y) - (a1.x*a1.x + a1.y*a1.y);
            #pragma unroll
            for (int o = 16; o; o >>= 1){
                cr += __shfl_xor_sync(FULLM, cr, o);
                ci += __shfl_xor_sync(FULLM, ci, o);
                zz += __shfl_xor_sync(FULLM, zz, o);
            }
            if (lane == 0){ red3[w*3] = cr; red3[w*3+1] = ci; red3[w*3+2] = zz; }
        }
        __syncthreads();
        if (t == 0){
            exps[wq]      = 2.f*(red3[0] + red3[3] + red3[6] + red3[9]);
            exps[8 + wq]  = 2.f*(red3[1] + red3[4] + red3[7] + red3[10]);
            exps[16 + wq] =      red3[2] + red3[5] + red3[8] + red3[11];
        }
        __syncthreads();
    }

    // ---- FF1 ----
    {
        float a = ff1b[t];
        const float* wr = ff1W + t*24;
        #pragma unroll
        for (int m2 = 0; m2 < 24; m2++) a += exps[m2] * wr[m2];
        g_h[b*EMB + t] = fmaxf(a, 0.f);
    }
}

// =====================================================================
// Kernel 2: FF2. 512 thr = 16 warps; warp tile 4v x 4 b-pairs; block 32v x 16b.
// W via LDG.128 (double-buffered), h via LDS.128, 2-round smem reduction.
// =====================================================================
__global__ void __launch_bounds__(512) ff2_kernel(const float* __restrict__ W,
                                                  const float* __restrict__ bias,
                                                  float* __restrict__ out,
                                                  int write_scalar){
    __shared__ __align__(16) char sbuf[4608*8];   // 36 KB: hp (32K) then red
    __shared__ float shout[512];
    float2 (*hp)[EMB] = (float2 (*)[EMB])sbuf;
    ull* red = (ull*)sbuf;

    int t = threadIdx.x;
    int wid = t >> 5, lane = t & 31;

    for (int idx = t; idx < 8*EMB; idx += 512){
        int bj = idx >> 9, k = idx & 511;
        hp[bj][k] = make_float2(g_h[(2*bj)*EMB + k], g_h[(2*bj+1)*EMB + k]);
    }
    if (write_scalar && blockIdx.x == 0 && t == 0){
        float s = 0.f;
        #pragma unroll
        for (int b = 0; b < NB; b++) s += g_fp[b];
        out[NOUT_OP] = s * (1.f/16.f);
    }
    __syncthreads();

    int vbase = blockIdx.x*32 + (wid >> 1)*4;
    int bjb   = (wid & 1)*4;

    ull acc[4][4];
    #pragma unroll
    for (int vi = 0; vi < 4; vi++)
        #pragma unroll
        for (int j = 0; j < 4; j++) acc[vi][j] = 0ULL;

    float4 wv[4], wvn[4];
    {
        int k0 = lane*4;
        #pragma unroll
        for (int vi = 0; vi < 4; vi++){
            int v = vbase + vi;
            wv[vi] = (v < NVOCAB) ? *(const float4*)&W[(size_t)v*EMB + k0]
                                  : make_float4(0.f,0.f,0.f,0.f);
        }
    }
    #pragma unroll
    for (int it = 0; it < 4; it++){
        if (it < 3){
            int kn = (it+1)*128 + lane*4;
            #pragma unroll
            for (int vi = 0; vi < 4; vi++){
                int v = vbase + vi;
                wvn[vi] = (v < NVOCAB) ? *(const float4*)&W[(size_t)v*EMB + kn]
                                       : make_float4(0.f,0.f,0.f,0.f);
            }
        }
        int k0 = it*128 + lane*4;
        ull h2[4][4];
        #pragma unroll
        for (int j = 0; j < 4; j++){
            ulonglong2 ha = *(const ulonglong2*)&hp[bjb + j][k0];
            ulonglong2 hb = *(const ulonglong2*)&hp[bjb + j][k0 + 2];
            h2[j][0] = ha.x; h2[j][1] = ha.y; h2[j][2] = hb.x; h2[j][3] = hb.y;
        }
        #pragma unroll
        for (int vi = 0; vi < 4; vi++){
            float4 w4 = wv[vi];
            ull w2;
            w2 = pack2(w4.x, w4.x);
            #pragma unroll
            for (int j = 0; j < 4; j++) fma2(acc[vi][j], w2, h2[j][0]);
            w2 = pack2(w4.y, w4.y);
            #pragma unroll
            for (int j = 0; j < 4; j++) fma2(acc[vi][j], w2, h2[j][1]);
            w2 = pack2(w4.z, w4.z);
            #pragma unroll
            for (int j = 0; j < 4; j++) fma2(acc[vi][j], w2, h2[j][2]);
            w2 = pack2(w4.w, w4.w);
            #pragma unroll
            for (int j = 0; j < 4; j++) fma2(acc[vi][j], w2, h2[j][3]);
        }
        #pragma unroll
        for (int vi = 0; vi < 4; vi++) wv[vi] = wvn[vi];
    }
    __syncthreads();   // hp dead

    // 2-round reduction: round 0 -> vi {0,1}, round 1 -> vi {2,3}
    #pragma unroll 1
    for (int round = 0; round < 2; round++){
        #pragma unroll
        for (int vi2 = 0; vi2 < 2; vi2++)
            #pragma unroll
            for (int j = 0; j < 4; j++)
                red[t*9 + vi2*4 + j] = acc[round*2 + vi2][j];
        __syncthreads();
        if (t < 128){
            int bj = t & 7, q = t >> 3;        // q = vgroup*2 + vi2
            int vgroup = q >> 1, vi2 = q & 1;
            int vloc = vgroup*4 + round*2 + vi2;
            int wsrc = vgroup*2 + (bj >> 2);
            int idx = vi2*4 + (bj & 3);
            ull sum = 0ULL;
            #pragma unroll
            for (int ln = 0; ln < 32; ln++)
                sum = add2(sum, red[(wsrc*32 + ln)*9 + idx]);
            int v = blockIdx.x*32 + vloc;
            float bv = (v < NVOCAB) ? bias[v] : 0.f;
            float lo, hi; unpack2(sum, lo, hi);
            shout[(2*bj)*32 + vloc]     = lo + bv;
            shout[(2*bj + 1)*32 + vloc] = hi + bv;
        }
        __syncthreads();
    }

    // coalesced stores: 128B run per batch row
    {
        int b_ = t >> 5, vloc = t & 31;
        int v = blockIdx.x*32 + vloc;
        if (v < NVOCAB)
            out[(size_t)b_*NVOCAB + v] = shout[b_*32 + vloc];
    }
}

// ---------------- launch ----------------
extern "C" void kernel_launch(void* const* d_in, const int* in_sizes, int n_in,
                              void* d_out, int out_size){
    const int*   x    = (const int*)  d_in[0];
    const float* embW = (const float*)d_in[1];
    const float* e2rW = (const float*)d_in[2];
    const float* e2rb = (const float*)d_in[3];
    const float* poly = (const float*)d_in[4];
    const float* mix  = (const float*)d_in[5];
    const float* qff  = (const float*)d_in[6];
    const float* ff1W = (const float*)d_in[7];
    const float* ff1b = (const float*)d_in[8];
    const float* ff2W = (const float*)d_in[9];
    const float* ff2b = (const float*)d_in[10];
    float* out = (float*)d_out;

    mid_kernel<<<NB, 512>>>(x, embW, e2rW, e2rb, mix, poly, qff, ff1W, ff1b);

    int ws = (out_size > NOUT_OP) ? 1 : 0;
    ff2_kernel<<<(NVOCAB + 31)/32, 512>>>(ff2W, ff2b, out, ws);
}

// round 10
// speedup vs baseline: 1.4195x; 1.4195x over previous
#include <cuda_runtime.h>
#include <cstdint>

typedef unsigned long long ull;
#define FULLM 0xffffffffu

#define NQ 8
#define DIM 256
#define NW 16
#define NB 16
#define NROTS 64
#define EMB 512
#define NVOCAB 50257
#define NOUT_OP (NB*NVOCAB)

// ---------------- scratch ----------------
__device__ float g_fp[NB];
__device__ __align__(16) float g_h[NB*EMB];   // h[b][k]

// ---------------- f32x2 helpers ----------------
__device__ __forceinline__ ull pack2(float a, float b){
    ull r; asm("mov.b64 %0, {%1,%2};" : "=l"(r) : "f"(a), "f"(b)); return r;
}
__device__ __forceinline__ void unpack2(ull v, float &a, float &b){
    asm("mov.b64 {%0,%1}, %2;" : "=f"(a), "=f"(b) : "l"(v));
}
__device__ __forceinline__ void fma2(ull &d, ull a, ull b){
    asm("fma.rn.f32x2 %0, %1, %2, %0;" : "+l"(d) : "l"(a), "l"(b));
}
__device__ __forceinline__ ull add2(ull a, ull b){
    ull r; asm("add.rn.f32x2 %0, %1, %2;" : "=l"(r) : "l"(a), "l"(b)); return r;
}

// =====================================================================
// Warp-resident quantum gates. amp index a = lane*8 + r
// =====================================================================
template<int P>
__device__ __forceinline__ void ry_gate(float2* s, float c, float sn, int lane){
    if constexpr (P < 3){
        #pragma unroll
        for (int r = 0; r < 8; r++)
            if (!(r & (1<<P))){
                const int r1 = r | (1<<P);
                float2 a0 = s[r], a1 = s[r1];
                s[r]  = make_float2(c*a0.x - sn*a1.x, c*a0.y - sn*a1.y);
                s[r1] = make_float2(sn*a0.x + c*a1.x, sn*a0.y + c*a1.y);
            }
    } else {
        const int M = 1 << (P-3);
        float sg = (lane & M) ? sn : -sn;
        #pragma unroll
        for (int r = 0; r < 8; r++){
            float px = __shfl_xor_sync(FULLM, s[r].x, M);
            float py = __shfl_xor_sync(FULLM, s[r].y, M);
            s[r] = make_float2(c*s[r].x + sg*px, c*s[r].y + sg*py);
        }
    }
}

template<int PC, int PT>
__device__ __forceinline__ void crx_gate(float2* s, float c, float sn, int lane){
    if constexpr (PT < 3 && PC < 3){
        #pragma unroll
        for (int r = 0; r < 8; r++)
            if ((r & (1<<PC)) && !(r & (1<<PT))){
                const int r1 = r | (1<<PT);
                float2 a0 = s[r], a1 = s[r1];
                s[r]  = make_float2(c*a0.x + sn*a1.y, c*a0.y - sn*a1.x);
                s[r1] = make_float2(c*a1.x + sn*a0.y, c*a1.y - sn*a0.x);
            }
    } else if constexpr (PT < 3 && PC >= 3){
        if (lane & (1 << (PC-3))){
            #pragma unroll
            for (int r = 0; r < 8; r++)
                if (!(r & (1<<PT))){
                    const int r1 = r | (1<<PT);
                    float2 a0 = s[r], a1 = s[r1];
                    s[r]  = make_float2(c*a0.x + sn*a1.y, c*a0.y - sn*a1.x);
                    s[r1] = make_float2(c*a1.x + sn*a0.y, c*a1.y - sn*a0.x);
                }
        }
    } else if constexpr (PT >= 3 && PC < 3){
        const int M = 1 << (PT-3);
        #pragma unroll
        for (int r = 0; r < 8; r++){
            float px = __shfl_xor_sync(FULLM, s[r].x, M);
            float py = __shfl_xor_sync(FULLM, s[r].y, M);
            if (r & (1<<PC))
                s[r] = make_float2(c*s[r].x + sn*py, c*s[r].y - sn*px);
        }
    } else {
        const int M = 1 << (PT-3);
        bool ctl = (lane & (1 << (PC-3))) != 0;
        #pragma unroll
        for (int r = 0; r < 8; r++){
            float px = __shfl_xor_sync(FULLM, s[r].x, M);
            float py = __shfl_xor_sync(FULLM, s[r].y, M);
            if (ctl)
                s[r] = make_float2(c*s[r].x + sn*py, c*s[r].y - sn*px);
        }
    }
}

__device__ __forceinline__ void layer(float2* s, const float2* ang, int lane){
    float2 a;
    #define RYG(P, I)     { a = ang[I]; ry_gate<P>(s, a.x, a.y, lane); }
    #define CRXG(PC,PT,I) { a = ang[I]; crx_gate<PC,PT>(s, a.x, a.y, lane); }
    RYG(7,0) RYG(6,1) RYG(5,2) RYG(4,3) RYG(3,4) RYG(2,5) RYG(1,6) RYG(0,7)
    CRXG(0,7,8) CRXG(1,0,9) CRXG(2,1,10) CRXG(3,2,11)
    CRXG(4,3,12) CRXG(5,4,13) CRXG(6,5,14) CRXG(7,6,15)
    RYG(7,16) RYG(6,17) RYG(5,18) RYG(4,19) RYG(3,20) RYG(2,21) RYG(1,22) RYG(0,23)
    CRXG(0,1,24) CRXG(7,0,25) CRXG(6,7,26) CRXG(5,6,27)
    CRXG(4,5,28) CRXG(3,4,29) CRXG(2,3,30) CRXG(1,2,31)
    #undef RYG
    #undef CRXG
}

// =====================================================================
// Kernel 1: EVERYTHING except FF2. 16 blocks x 512 thr.
// =====================================================================
union MidU {
    float2 embp[8][EMB];
    float2 st[NW][DIM];
};

__global__ void __launch_bounds__(512) mid_kernel(const int* __restrict__ x,
                           const float* __restrict__ embW,
                           const float* __restrict__ e2rW,
                           const float* __restrict__ e2rb,
                           const float* __restrict__ mix,
                           const float* __restrict__ poly,
                           const float* __restrict__ qff,
                           const float* __restrict__ ff1W,
                           const float* __restrict__ ff1b){
    __shared__ MidU u;
    __shared__ float2 sh_ang[NW][NROTS];
    __shared__ float2 sh_comb[DIM];
    __shared__ float2 sh_cf[NW];
    __shared__ float2 sh_qang[32];
    __shared__ float  redv[16];
    __shared__ float  red3[12];
    __shared__ float  exps[24];
    __shared__ float  sh_inv;

    int b = blockIdx.x;
    int t = threadIdx.x;
    int w = t >> 5, lane = t & 31;

    {
        float* embf = (float*)u.embp;
        for (int idx = t; idx < NW*EMB; idx += 512){
            int w_ = idx >> 9, k = idx & 511;
            float val = embW[(size_t)x[b*NW + w_]*EMB + k];
            embf[((w_ >> 1)*EMB + k)*2 + (w_ & 1)] = val;
        }
    }
    if (t < 32){
        float re = 0.f, im = 0.f, a = 0.f;
        if (t < NW){ re = mix[2*t]; im = mix[2*t+1]; a = sqrtf(re*re + im*im); }
        float s = a;
        #pragma unroll
        for (int o = 16; o; o >>= 1) s += __shfl_xor_sync(FULLM, s, o);
        float inv = 1.f / fmaxf(s, 1e-12f);
        if (t < NW) sh_cf[t] = make_float2(re*inv, im*inv);
    }
    if (t >= 32 && t < 64){
        int i = t - 32;
        float sv, cv; sincosf(qff[i]*0.5f, &sv, &cv);
        sh_qang[i] = make_float2(cv, sv);
    }
    __syncthreads();

    {
        ull acc2[4][8];
        #pragma unroll
        for (int rr = 0; rr < 4; rr++)
            #pragma unroll
            for (int wp = 0; wp < 8; wp++) acc2[rr][wp] = 0ULL;

        #pragma unroll 4
        for (int it = 0; it < 16; it++){
            int k = it*32 + lane;
            float wr_[4];
            #pragma unroll
            for (int rr = 0; rr < 4; rr++)
                wr_[rr] = e2rW[(size_t)(w*4 + rr)*EMB + k];
            ull e2[8];
            #pragma unroll
            for (int wp = 0; wp < 8; wp++)
                e2[wp] = *(const ull*)&u.embp[wp][k];
            #pragma unroll
            for (int rr = 0; rr < 4; rr++){
                ull w2 = pack2(wr_[rr], wr_[rr]);
                #pragma unroll
                for (int wp = 0; wp < 8; wp++)
                    fma2(acc2[rr][wp], w2, e2[wp]);
            }
        }
        #pragma unroll
        for (int o = 16; o; o >>= 1)
            #pragma unroll
            for (int rr = 0; rr < 4; rr++)
                #pragma unroll
                for (int wp = 0; wp < 8; wp++)
                    acc2[rr][wp] = add2(acc2[rr][wp], __shfl_xor_sync(FULLM, acc2[rr][wp], o));
        int lrr = lane >> 3, lwp = lane & 7;
        ull v = 0ULL;
        #pragma unroll
        for (int rr = 0; rr < 4; rr++)
            #pragma unroll
            for (int wp = 0; wp < 8; wp++)
                if (rr == lrr && wp == lwp) v = acc2[rr][wp];
        int r = w*4 + lrr;
        float bias_r = e2rb[r];
        float lo, hi; unpack2(v, lo, hi);
        float s0, c0, s1, c1;
        sincosf((lo + bias_r)*0.5f, &s0, &c0);
        sincosf((hi + bias_r)*0.5f, &s1, &c1);
        sh_ang[2*lwp][r]     = make_float2(c0, s0);
        sh_ang[2*lwp + 1][r] = make_float2(c1, s1);
    }
    __syncthreads();

    float2 pacc = make_float2((t == 0) ? poly[0] : 0.f, 0.f);

    #pragma unroll 1
    for (int d = 1; d <= 3; d++){
        float2 s[8];
        if (d == 1){
            #pragma unroll
            for (int r = 0; r < 8; r++)
                s[r] = make_float2((lane == 0 && r == 0) ? 1.f : 0.f, 0.f);
        } else {
            #pragma unroll
            for (int r = 0; r < 8; r++) s[r] = sh_comb[lane*8 + r];
        }
        #pragma unroll 1
        for (int l = 0; l < 2; l++)
            layer(s, &sh_ang[w][32*l], lane);
        #pragma unroll
        for (int r = 0; r < 8; r++) u.st[w][lane*8 + r] = s[r];
        __syncthreads();
        if (t < DIM){
            float2 acc2 = make_float2(0.f, 0.f);
            #pragma unroll
            for (int ww = 0; ww < NW; ww++){
                float2 c = sh_cf[ww];
                float2 v = u.st[ww][t];
                acc2.x += c.x*v.x - c.y*v.y;
                acc2.y += c.x*v.y + c.y*v.x;
            }
            float pd = poly[d];
            pacc.x += pd*acc2.x; pacc.y += pd*acc2.y;
            sh_comb[t] = acc2;
        }
        __syncthreads();
    }

    float psum = fabsf(poly[0]) + fabsf(poly[1]) + fabsf(poly[2]) + fabsf(poly[3]);
    float invp = 1.f / psum;
    float2 m = make_float2(pacc.x*invp, pacc.y*invp);
    if (t < DIM){
        float loc = m.x*m.x + m.y*m.y;
        #pragma unroll
        for (int o = 16; o; o >>= 1) loc += __shfl_xor_sync(FULLM, loc, o);
        if (lane == 0) redv[w] = loc;
    }
    __syncthreads();
    if (t == 0){
        float fp = sqrtf(redv[0]+redv[1]+redv[2]+redv[3]+redv[4]+redv[5]+redv[6]+redv[7]);
        g_fp[b] = fp;
        sh_inv = 1.f / fmaxf(fp, 1e-12f);
    }
    __syncthreads();
    if (t < DIM) sh_comb[t] = make_float2(m.x*sh_inv, m.y*sh_inv);
    __syncthreads();

    if (w == 0){
        float2 s[8];
        #pragma unroll
        for (int r = 0; r < 8; r++) s[r] = sh_comb[lane*8 + r];
        layer(s, sh_qang, lane);
        #pragma unroll
        for (int r = 0; r < 8; r++) sh_comb[lane*8 + r] = s[r];
    }
    __syncthreads();

    for (int wq = 0; wq < 8; wq++){
        int p = 7 - wq;
        if (t < 128){
            int i0 = ((t >> p) << (p+1)) | (t & ((1 << p) - 1));
            int i1 = i0 | (1 << p);
            float2 a0 = sh_comb[i0], a1 = sh_comb[i1];
            float cr = a0.x*a1.x + a0.y*a1.y;
            float ci = a0.x*a1.y - a0.y*a1.x;
            float zz = (a0.x*a0.x + a0.y*a0.y) - (a1.x*a1.x + a1.y*a1.y);
            #pragma unroll
            for (int o = 16; o; o >>= 1){
                cr += __shfl_xor_sync(FULLM, cr, o);
                ci += __shfl_xor_sync(FULLM, ci, o);
                zz += __shfl_xor_sync(FULLM, zz, o);
            }
            if (lane == 0){ red3[w*3] = cr; red3[w*3+1] = ci; red3[w*3+2] = zz; }
        }
        __syncthreads();
        if (t == 0){
            exps[wq]      = 2.f*(red3[0] + red3[3] + red3[6] + red3[9]);
            exps[8 + wq]  = 2.f*(red3[1] + red3[4] + red3[7] + red3[10]);
            exps[16 + wq] =      red3[2] + red3[5] + red3[8] + red3[11];
        }
        __syncthreads();
    }

    {
        float a = ff1b[t];
        const float* wr = ff1W + t*24;
        #pragma unroll
        for (int m2 = 0; m2 < 24; m2++) a += exps[m2] * wr[m2];
        g_h[b*EMB + t] = fmaxf(a, 0.f);
    }
}

// =====================================================================
// Kernel 2: FF2. k-paired f32x2, zero packing movs.
// 256 thr = 8 warps; warp = (vgrp = wid>>2) x (bgrp = wid&3);
// thread tile 4v x 4b; block tile 8v x 16b. acc[vi][bi] holds (even-k, odd-k).
// =====================================================================
union FF2U {
    float  hp[NB][EMB];       // 32 KB: h[b][k], linear copy of g_h
    float  red[256*17];       // 17.4 KB: stride-17 partials (after mainloop)
};

__global__ void __launch_bounds__(256, 3) ff2_kernel(const float* __restrict__ W,
                                                     const float* __restrict__ bias,
                                                     float* __restrict__ out,
                                                     int write_scalar){
    __shared__ FF2U u;
    int t = threadIdx.x;
    int wid = t >> 5, lane = t & 31;

    // stage h: straight float4 copy (L2-resident source)
    {
        const float4* src = (const float4*)g_h;
        float4* dst = (float4*)u.hp;
        #pragma unroll
        for (int i = 0; i < 8; i++)
            dst[t + i*256] = src[t + i*256];
    }
    if (write_scalar && blockIdx.x == 0 && t == 0){
        float s = 0.f;
        #pragma unroll
        for (int b = 0; b < NB; b++) s += g_fp[b];
        out[NOUT_OP] = s * (1.f/16.f);
    }
    __syncthreads();

    int vgrp = wid >> 2, bgrp = wid & 3;
    int vbase = blockIdx.x*8 + vgrp*4;

    ull acc[4][4];
    #pragma unroll
    for (int vi = 0; vi < 4; vi++)
        #pragma unroll
        for (int bi = 0; bi < 4; bi++) acc[vi][bi] = 0ULL;

    // row pointers (clamped; out-of-range rows computed but never stored)
    const ulonglong2* wrow[4];
    #pragma unroll
    for (int vi = 0; vi < 4; vi++){
        int v = vbase + vi; if (v > NVOCAB-1) v = NVOCAB-1;
        wrow[vi] = (const ulonglong2*)(W + (size_t)v*EMB);
    }

    #pragma unroll
    for (int it = 0; it < 4; it++){
        int kq = it*32 + lane;          // float4 index within row (k = kq*4)
        ulonglong2 wl[4];
        #pragma unroll
        for (int vi = 0; vi < 4; vi++) wl[vi] = wrow[vi][kq];
        ulonglong2 hl[4];
        #pragma unroll
        for (int bi = 0; bi < 4; bi++)
            hl[bi] = *(const ulonglong2*)&u.hp[bgrp*4 + bi][kq*4];
        #pragma unroll
        for (int vi = 0; vi < 4; vi++){
            #pragma unroll
            for (int bi = 0; bi < 4; bi++){
                fma2(acc[vi][bi], wl[vi].x, hl[bi].x);
                fma2(acc[vi][bi], wl[vi].y, hl[bi].y);
            }
        }
    }
    __syncthreads();   // hp dead

    // fold (even,odd) halves and dump with stride 17 (conflict-free: 17 odd)
    #pragma unroll
    for (int vi = 0; vi < 4; vi++)
        #pragma unroll
        for (int bi = 0; bi < 4; bi++){
            float lo, hi; unpack2(acc[vi][bi], lo, hi);
            u.red[t*17 + vi*4 + bi] = lo + hi;
        }
    __syncthreads();

    // 128 threads: one (vloc, b) output each, reduce over 32 lanes
    if (t < 128){
        int b_ = t >> 3, vloc = t & 7;
        int wsrc = (vloc >> 2)*4 + (b_ >> 2);
        int idx  = (vloc & 3)*4 + (b_ & 3);
        float sum = 0.f;
        #pragma unroll
        for (int ln = 0; ln < 32; ln++)
            sum += u.red[(wsrc*32 + ln)*17 + idx];
        int v = blockIdx.x*8 + vloc;
        if (v < NVOCAB)
            out[(size_t)b_*NVOCAB + v] = sum + bias[v];
    }
}

// ---------------- launch ----------------
extern "C" void kernel_launch(void* const* d_in, const int* in_sizes, int n_in,
                              void* d_out, int out_size){
    const int*   x    = (const int*)  d_in[0];
    const float* embW = (const float*)d_in[1];
    const float* e2rW = (const float*)d_in[2];
    const float* e2rb = (const float*)d_in[3];
    const float* poly = (const float*)d_in[4];
    const float* mix  = (const float*)d_in[5];
    const float* qff  = (const float*)d_in[6];
    const float* ff1W = (const float*)d_in[7];
    const float* ff1b = (const float*)d_in[8];
    const float* ff2W = (const float*)d_in[9];
    const float* ff2b = (const float*)d_in[10];
    float* out = (float*)d_out;

    mid_kernel<<<NB, 512>>>(x, embW, e2rW, e2rb, mix, poly, qff, ff1W, ff1b);

    int ws = (out_size > NOUT_OP) ? 1 : 0;
    ff2_kernel<<<(NVOCAB + 7)/8, 256>>>(ff2W, ff2b, out, ws);
}